// round 15
// baseline (speedup 1.0000x reference)
#include <cuda_runtime.h>
#include <cuda_bf16.h>
#include <math.h>

#define NN    10000
#define EE    320000
#define ETOT  330000
#define DIN   256
#define HEADS 8
#define C1    64
#define F1    512
#define F1P   1024            // packed xl|xr GEMM width
#define DOUT  32
#define D2P   64              // packed h2l|h2r row
#define NEG   0.2f

// ---------------- scratch ----------------
__device__ int             g_src[ETOT];
__device__ int             g_dst[ETOT];
__device__ int             g_mode64;
__device__ int             g_deg[NN];
__device__ int             g_off[NN + 1];
__device__ int             g_cur[NN];
__device__ int             g_csrc[ETOT];          // src id sorted by dst
__device__ __nv_bfloat16   g_W1Tb[F1P * DIN];     // [n][k] transposed bf16 [1024][256]
__device__ __nv_bfloat16   g_W2Tb[D2P * F1];      // [n][k] transposed bf16 [64][512]
__device__ __nv_bfloat16   g_xb[NN * DIN];        // x converted to bf16
__device__ __nv_bfloat162  g_xlb[NN * (F1 / 2)];  // xl half, bf16x2 (gather operand)
__device__ float           g_xr[NN * F1];         // xr half, fp32
__device__ __nv_bfloat16   g_h1b[NN * F1];        // elu'd h1, bf16 (GEMM2 A operand)
__device__ float           g_h2[NN * D2P];        // per node: [h2l(32) | h2r(32)]

__device__ __forceinline__ float lrelu(float v) { return v > 0.f ? v : NEG * v; }

// ---------------- probe edge dtype (1 warp) ----------------
__global__ void k_prep(const void* __restrict__ ei) {
    if (threadIdx.x == 0) {
        const long long* p64 = (const long long*)ei;
        int ok = 1;
        for (int j = 0; j < 64; j++) {
            long long v = p64[j];
            if (v < 0 || v >= NN) { ok = 0; break; }
        }
        g_mode64 = ok;
    }
}

// ---------------- decode + degree count ----------------
__global__ void k_decode_count(const void* __restrict__ ei) {
    int e = blockIdx.x * blockDim.x + threadIdx.x;
    if (e >= ETOT) return;
    int s, d;
    if (e >= EE) { s = d = e - EE; }
    else if (g_mode64) {
        s = (int)((const long long*)ei)[e];
        d = (int)((const long long*)ei)[EE + e];
    } else {
        s = ((const int*)ei)[e];
        d = ((const int*)ei)[EE + e];
    }
    g_src[e] = s;
    g_dst[e] = d;
    atomicAdd(&g_deg[d], 1);
}

// ---------------- scan (re-zeroes g_deg for next replay) ----------------
#define SCAN_T 1024
#define SCAN_PER ((NN + SCAN_T - 1) / SCAN_T)
__global__ void k_scan() {
    __shared__ int s[SCAN_T];
    int t = threadIdx.x;
    int base = t * SCAN_PER;
    int deg[SCAN_PER];
    int sum = 0;
#pragma unroll
    for (int i = 0; i < SCAN_PER; i++) {
        int idx = base + i;
        deg[i] = (idx < NN) ? g_deg[idx] : 0;
        sum += deg[i];
        if (idx < NN) g_deg[idx] = 0;
    }
    s[t] = sum;
    __syncthreads();
    for (int o = 1; o < SCAN_T; o <<= 1) {
        int v = (t >= o) ? s[t - o] : 0;
        __syncthreads();
        s[t] += v;
        __syncthreads();
    }
    int run = s[t] - sum;
#pragma unroll
    for (int i = 0; i < SCAN_PER; i++) {
        int idx = base + i;
        if (idx < NN) {
            g_off[idx] = run;
            g_cur[idx] = run;
            run += deg[i];
        }
    }
    if (t == SCAN_T - 1) g_off[NN] = ETOT;
}

__global__ void k_fill() {
    int e = blockIdx.x * blockDim.x + threadIdx.x;
    if (e >= ETOT) return;
    int pos = atomicAdd(&g_cur[g_dst[e]], 1);
    g_csrc[pos] = g_src[e];
}

// ---------------- merged: transpose-pack W1,W2 (bf16 [n][k]) + convert x->bf16 ----------------
#define PACKB_W1 256
#define PACKB_W2 32
#define PACKB_X  2500
__global__ void k_pack_all(const float* __restrict__ W1l, const float* __restrict__ W1r,
                           const float* __restrict__ W2l, const float* __restrict__ W2r,
                           const float* __restrict__ x) {
    __shared__ float tile[32][33];
    int b = blockIdx.x;
    int tid = threadIdx.x;
    if (b < PACKB_W1) {
        int n0 = (b & 31) * 32, k0 = (b >> 5) * 32;
        int tx = tid & 31, ty = tid >> 5;
#pragma unroll
        for (int i = 0; i < 32; i += 8) {
            int k = k0 + ty + i, n = n0 + tx;
            float v = (n < F1) ? W1l[k * F1 + n] : W1r[k * F1 + (n - F1)];
            tile[ty + i][tx] = v;
        }
        __syncthreads();
#pragma unroll
        for (int i = 0; i < 32; i += 8) {
            int n = n0 + ty + i, k = k0 + tx;
            g_W1Tb[(size_t)n * DIN + k] = __float2bfloat16(tile[tx][ty + i]);
        }
    } else if (b < PACKB_W1 + PACKB_W2) {
        int r = b - PACKB_W1;
        int n0 = (r & 1) * 32, k0 = (r >> 1) * 32;
        int tx = tid & 31, ty = tid >> 5;
#pragma unroll
        for (int i = 0; i < 32; i += 8) {
            int k = k0 + ty + i, n = n0 + tx;
            float v = (n < DOUT) ? W2l[k * DOUT + n] : W2r[k * DOUT + (n - DOUT)];
            tile[ty + i][tx] = v;
        }
        __syncthreads();
#pragma unroll
        for (int i = 0; i < 32; i += 8) {
            int n = n0 + ty + i, k = k0 + tx;
            g_W2Tb[(size_t)n * F1 + k] = __float2bfloat16(tile[tx][ty + i]);
        }
    } else {
        int idx = (b - PACKB_W1 - PACKB_W2) * 1024 + tid * 4;
        float4 v = *(const float4*)(x + idx);
        __nv_bfloat162 p0 = __floats2bfloat162_rn(v.x, v.y);
        __nv_bfloat162 p1 = __floats2bfloat162_rn(v.z, v.w);
        uint2 pk;
        pk.x = *(unsigned*)&p0;
        pk.y = *(unsigned*)&p1;
        *(uint2*)(g_xb + idx) = pk;
    }
}

// ---------------- bf16 tensor-core GEMM (templated M/N tiles, cp.async 2-stage) ----------------
#define TBK 64
__device__ __forceinline__ void cp16(unsigned dst, const void* src, unsigned sz) {
    asm volatile("cp.async.cg.shared.global [%0], [%1], 16, %2;\n"
                 :: "r"(dst), "l"(src), "r"(sz));
}
__device__ __forceinline__ void cp8(unsigned dst, const void* src) {
    asm volatile("cp.async.ca.shared.global [%0], [%1], 8;\n"
                 :: "r"(dst), "l"(src));
}
__device__ __forceinline__ void ldsm_x4(unsigned& r0, unsigned& r1, unsigned& r2, unsigned& r3,
                                        const void* p) {
    unsigned addr = (unsigned)__cvta_generic_to_shared(p);
    asm volatile("ldmatrix.sync.aligned.m8n8.x4.shared.b16 {%0,%1,%2,%3}, [%4];"
                 : "=r"(r0), "=r"(r1), "=r"(r2), "=r"(r3) : "r"(addr));
}

template <int BN, int TM>
__global__ void __launch_bounds__((TM / 64) * (BN / 32) * 32) k_gemm_bf16(
    const __nv_bfloat16* __restrict__ A,
    const __nv_bfloat16* __restrict__ Bt, float* __restrict__ Cf,
    int M, int K, int ncols_bf, int cf_stride) {
    constexpr int MW = TM / 64;               // warp rows
    constexpr int NW = BN / 32;               // warp cols
    constexpr int T = MW * NW * 32;           // threads
    constexpr int A_BYTES = TM * 128;
    constexpr int STAGE = A_BYTES + BN * 128;
    extern __shared__ char smem[];

    int tid = threadIdx.x;
    int warp = tid >> 5, lane = tid & 31;
    int wm = (warp % MW) * 64;
    int wn = (warp / MW) * 32;
    int bm = blockIdx.y * TM, bn = blockIdx.x * BN;
    int tr = lane >> 2, tc = lane & 3;

    float acc[4][4][4];
#pragma unroll
    for (int mt = 0; mt < 4; mt++)
#pragma unroll
        for (int nt = 0; nt < 4; nt++)
#pragma unroll
            for (int r = 0; r < 4; r++) acc[mt][nt][r] = 0.f;

    auto fill = [&](int stage, int k0) {
        char* base = smem + stage * STAGE;
#pragma unroll
        for (int c = tid; c < TM * 8; c += T) {
            int row = c >> 3, ch = c & 7;
            unsigned valid = (bm + row < M) ? 16u : 0u;
            cp16((unsigned)__cvta_generic_to_shared(base + row * 128 + (((ch ^ (row & 7))) << 4)),
                 A + (size_t)(bm + row) * K + k0 + ch * 8, valid);
        }
#pragma unroll
        for (int c = tid; c < BN * 8; c += T) {
            int row = c >> 3, ch = c & 7;
            cp16((unsigned)__cvta_generic_to_shared(base + A_BYTES + row * 128 + (((ch ^ (row & 7))) << 4)),
                 Bt + (size_t)(bn + row) * K + k0 + ch * 8, 16u);
        }
        asm volatile("cp.async.commit_group;\n");
    };

    int KT = K / TBK;
    fill(0, 0);
    for (int kt = 0; kt < KT; kt++) {
        if (kt + 1 < KT) {
            fill((kt + 1) & 1, (kt + 1) * TBK);
            asm volatile("cp.async.wait_group 1;\n");
        } else {
            asm volatile("cp.async.wait_group 0;\n");
        }
        __syncthreads();

        char* Ab_s = smem + (kt & 1) * STAGE;
        char* Bb_s = Ab_s + A_BYTES;
#pragma unroll
        for (int ks = 0; ks < TBK / 16; ks++) {
            unsigned a[4][4];
#pragma unroll
            for (int mt = 0; mt < 4; mt++) {
                int row = wm + mt * 16 + (lane & 15);
                int chunk = ks * 2 + (lane >> 4);
                ldsm_x4(a[mt][0], a[mt][1], a[mt][2], a[mt][3],
                        Ab_s + row * 128 + ((chunk ^ (row & 7)) << 4));
            }
            unsigned b[4][2];
#pragma unroll
            for (int j = 0; j < 2; j++) {
                int row = wn + j * 16 + ((lane >> 4) << 3) + (lane & 7);
                int chunk = ks * 2 + ((lane >> 3) & 1);
                unsigned r0, r1, r2, r3;
                ldsm_x4(r0, r1, r2, r3,
                        Bb_s + row * 128 + ((chunk ^ (row & 7)) << 4));
                b[2 * j][0] = r0; b[2 * j][1] = r1;
                b[2 * j + 1][0] = r2; b[2 * j + 1][1] = r3;
            }
#pragma unroll
            for (int mt = 0; mt < 4; mt++)
#pragma unroll
                for (int nt = 0; nt < 4; nt++) {
                    asm volatile(
                        "mma.sync.aligned.m16n8k16.row.col.f32.bf16.bf16.f32 "
                        "{%0,%1,%2,%3}, {%4,%5,%6,%7}, {%8,%9}, {%0,%1,%2,%3};\n"
                        : "+f"(acc[mt][nt][0]), "+f"(acc[mt][nt][1]),
                          "+f"(acc[mt][nt][2]), "+f"(acc[mt][nt][3])
                        : "r"(a[mt][0]), "r"(a[mt][1]), "r"(a[mt][2]), "r"(a[mt][3]),
                          "r"(b[nt][0]), "r"(b[nt][1]));
                }
        }
        __syncthreads();
    }

    bool bf_side = (bn < ncols_bf);
#pragma unroll
    for (int mt = 0; mt < 4; mt++) {
        int row0 = bm + wm + mt * 16 + tr;
#pragma unroll
        for (int nt = 0; nt < 4; nt++) {
            int col0 = bn + wn + nt * 8 + 2 * tc;
            if (bf_side) {
                if (row0 < M)
                    g_xlb[(size_t)row0 * (F1 / 2) + (col0 >> 1)] =
                        __floats2bfloat162_rn(acc[mt][nt][0], acc[mt][nt][1]);
                if (row0 + 8 < M)
                    g_xlb[(size_t)(row0 + 8) * (F1 / 2) + (col0 >> 1)] =
                        __floats2bfloat162_rn(acc[mt][nt][2], acc[mt][nt][3]);
            } else {
                int c = col0 - ncols_bf;
                if (row0 < M)
                    *(float2*)(Cf + (size_t)row0 * cf_stride + c) =
                        make_float2(acc[mt][nt][0], acc[mt][nt][1]);
                if (row0 + 8 < M)
                    *(float2*)(Cf + (size_t)(row0 + 8) * cf_stride + c) =
                        make_float2(acc[mt][nt][2], acc[mt][nt][3]);
            }
        }
    }
}

// ---------------- fused layer-1 attention: cp.async depth-4 gather pipeline ----------------
#define L1DEPTH 4
__global__ void __launch_bounds__(128) k_l1_fused(const float* __restrict__ att1,
                                                  const float* __restrict__ b1) {
    __shared__ char sbuf[L1DEPTH * 1024];    // 4 stages x 128 threads x 8B
    int node = blockIdx.x;
    int c4 = threadIdx.x;                    // owns channels [4*c4, 4*c4+4)
    int beg = g_off[node], end = g_off[node + 1];
    int len = end - beg;

    float4 xr = *(const float4*)(g_xr + (size_t)node * F1 + c4 * 4);
    float4 aw = __ldg(&((const float4*)att1)[c4]);

    unsigned sb = (unsigned)__cvta_generic_to_shared(sbuf) + c4 * 8;

    // prologue: stage edges 0..2 (pad with empty commits)
#pragma unroll
    for (int i = 0; i < 3; i++) {
        if (i < len) {
            int src = __ldg(&g_csrc[beg + i]);
            cp8(sb + (i & 3) * 1024, g_xlb + (size_t)src * (F1 / 2) + c4 * 2);
        }
        asm volatile("cp.async.commit_group;\n");
    }

    float m = -1e30f, den = 0.f;
    float4 acc = make_float4(0.f, 0.f, 0.f, 0.f);

    for (int i = 0; i < len; i++) {
        if (i + 3 < len) {
            int src = __ldg(&g_csrc[beg + i + 3]);
            cp8(sb + ((i + 3) & 3) * 1024, g_xlb + (size_t)src * (F1 / 2) + c4 * 2);
        }
        asm volatile("cp.async.commit_group;\n");
        asm volatile("cp.async.wait_group 3;\n");

        uint2 raw = *(const uint2*)(sbuf + (i & 3) * 1024 + c4 * 8);
        float2 f0 = __bfloat1622float2(*(const __nv_bfloat162*)&raw.x);
        float2 f1 = __bfloat1622float2(*(const __nv_bfloat162*)&raw.y);
        float part = lrelu(f0.x + xr.x) * aw.x + lrelu(f0.y + xr.y) * aw.y
                   + lrelu(f1.x + xr.z) * aw.z + lrelu(f1.y + xr.w) * aw.w;
#pragma unroll
        for (int o = 8; o; o >>= 1)
            part += __shfl_xor_sync(0xffffffffu, part, o);
        if (part > m) {
            float sc = __expf(m - part);
            den *= sc;
            acc.x *= sc; acc.y *= sc; acc.z *= sc; acc.w *= sc;
            m = part;
        }
        float w = __expf(part - m);
        den += w;
        acc.x += w * f0.x; acc.y += w * f0.y; acc.z += w * f1.x; acc.w += w * f1.y;
    }

    float inv = 1.f / (den + 1e-16f);
    float4 bb = __ldg(&((const float4*)b1)[c4]);
    float r0 = acc.x * inv + bb.x;
    float r1 = acc.y * inv + bb.y;
    float r2 = acc.z * inv + bb.z;
    float r3 = acc.w * inv + bb.w;
    r0 = r0 > 0.f ? r0 : expm1f(r0);
    r1 = r1 > 0.f ? r1 : expm1f(r1);
    r2 = r2 > 0.f ? r2 : expm1f(r2);
    r3 = r3 > 0.f ? r3 : expm1f(r3);
    __nv_bfloat162 o0 = __floats2bfloat162_rn(r0, r1);
    __nv_bfloat162 o1 = __floats2bfloat162_rn(r2, r3);
    uint2 pk;
    pk.x = *(unsigned*)&o0;
    pk.y = *(unsigned*)&o1;
    *(uint2*)(g_h1b + (size_t)node * F1 + c4 * 4) = pk;
}

// ---------------- fused layer-2 attention + bias + log_softmax ----------------
__global__ void k_l2_fused(float* __restrict__ out, const float* __restrict__ att2,
                           const float* __restrict__ b2) {
    int node = (blockIdx.x * blockDim.x + threadIdx.x) >> 5;
    int lane = threadIdx.x & 31;
    if (node >= NN) return;
    int beg = g_off[node], end = g_off[node + 1];

    float xr = g_h2[(size_t)node * D2P + DOUT + lane];
    float aw = __ldg(att2 + lane);

    float m = -1e30f, den = 0.f, acc = 0.f;
    for (int p = beg; p < end; p++) {
        int src = g_csrc[p];
        float v = g_h2[(size_t)src * D2P + lane];
        float part = lrelu(v + xr) * aw;
#pragma unroll
        for (int o = 16; o; o >>= 1)
            part += __shfl_xor_sync(0xffffffffu, part, o);
        if (part > m) {
            float sc = __expf(m - part);
            den *= sc; acc *= sc; m = part;
        }
        float w = __expf(part - m);
        den += w;
        acc += w * v;
    }
    float v = acc / (den + 1e-16f) + __ldg(b2 + lane);
    float mx = v;
#pragma unroll
    for (int o = 16; o; o >>= 1) mx = fmaxf(mx, __shfl_xor_sync(0xffffffffu, mx, o));
    float s = __expf(v - mx);
#pragma unroll
    for (int o = 16; o; o >>= 1) s += __shfl_xor_sync(0xffffffffu, s, o);
    out[node * DOUT + lane] = v - mx - __logf(s);
}

// ---------------- launch ----------------
extern "C" void kernel_launch(void* const* d_in, const int* in_sizes, int n_in,
                              void* d_out, int out_size) {
    const float* x    = (const float*)d_in[0];
    const void*  ei   = d_in[1];
    const float* W1l  = (const float*)d_in[2];
    const float* W1r  = (const float*)d_in[3];
    const float* att1 = (const float*)d_in[4];
    const float* b1   = (const float*)d_in[5];
    const float* W2l  = (const float*)d_in[6];
    const float* W2r  = (const float*)d_in[7];
    const float* att2 = (const float*)d_in[8];
    const float* b2   = (const float*)d_in[9];
    float*       out  = (float*)d_out;

    const int TPB = 256;

    float *xr, *h2;
    __nv_bfloat16 *w1t, *w2t, *h1b, *xb;
    cudaGetSymbolAddress((void**)&xr,  g_xr);
    cudaGetSymbolAddress((void**)&h2,  g_h2);
    cudaGetSymbolAddress((void**)&w1t, g_W1Tb);
    cudaGetSymbolAddress((void**)&w2t, g_W2Tb);
    cudaGetSymbolAddress((void**)&h1b, g_h1b);
    cudaGetSymbolAddress((void**)&xb,  g_xb);

    const int SM1 = 2 * (128 * 128 + 128 * 128);   // 65536
    const int SM2 = 2 * (64 * 128 + 64 * 128);     // 32768
    cudaFuncSetAttribute(k_gemm_bf16<128, 128>, cudaFuncAttributeMaxDynamicSharedMemorySize, SM1);
    cudaFuncSetAttribute(k_gemm_bf16<64, 64>,   cudaFuncAttributeMaxDynamicSharedMemorySize, SM2);

    k_prep<<<1, 32>>>(ei);                                              // 1
    k_decode_count<<<(ETOT + TPB - 1) / TPB, TPB>>>(ei);                // 2
    k_pack_all<<<PACKB_W1 + PACKB_W2 + PACKB_X, TPB>>>(W1l, W1r, W2l, W2r, x); // 3
    {
        dim3 grid(F1P / 128, (NN + 127) / 128);
        k_gemm_bf16<128, 128><<<grid, 256, SM1>>>(xb, w1t, xr, NN, DIN, F1, F1); // 4
    }
    k_scan<<<1, SCAN_T>>>();                                            // 5
    k_fill<<<(ETOT + TPB - 1) / TPB, TPB>>>();                          // 6
    k_l1_fused<<<NN, 128>>>(att1, b1);                                  // 7
    {
        dim3 grid(1, (NN + 63) / 64);
        k_gemm_bf16<64, 64><<<grid, 64, SM2>>>(h1b, w2t, h2, NN, F1, 0, D2P); // 8
    }
    k_l2_fused<<<(NN * 32 + TPB - 1) / TPB, TPB>>>(out, att2, b2);      // 9
}

// round 16
// speedup vs baseline: 1.1230x; 1.1230x over previous
#include <cuda_runtime.h>
#include <cuda_bf16.h>
#include <math.h>

#define NN    10000
#define EE    320000
#define ETOT  330000
#define DIN   256
#define HEADS 8
#define C1    64
#define F1    512
#define F1P   1024            // packed xl|xr GEMM width
#define DOUT  32
#define D2P   64              // packed h2l|h2r row
#define NEG   0.2f

// ---------------- scratch ----------------
__device__ int             g_src[ETOT];
__device__ int             g_dst[ETOT];
__device__ int             g_mode64;
__device__ int             g_deg[NN];
__device__ int             g_off[NN + 1];
__device__ int             g_cur[NN];
__device__ int             g_csrc[ETOT];          // src id sorted by dst
__device__ __nv_bfloat16   g_W1Tb[F1P * DIN];     // [n][k] transposed bf16 [1024][256]
__device__ __nv_bfloat16   g_W2Tb[D2P * F1];      // [n][k] transposed bf16 [64][512]
__device__ __nv_bfloat16   g_xb[NN * DIN];        // x converted to bf16
__device__ __nv_bfloat162  g_xlb[NN * (F1 / 2)];  // xl half, bf16x2 (gather operand)
__device__ float           g_xr[NN * F1];         // xr half, fp32
__device__ __nv_bfloat16   g_h1b[NN * F1];        // elu'd h1, bf16 (GEMM2 A operand)
__device__ float           g_h2[NN * D2P];        // per node: [h2l(32) | h2r(32)]

__device__ __forceinline__ float lrelu(float v) { return v > 0.f ? v : NEG * v; }

// ---------------- probe edge dtype (1 warp) ----------------
__global__ void k_prep(const void* __restrict__ ei) {
    if (threadIdx.x == 0) {
        const long long* p64 = (const long long*)ei;
        int ok = 1;
        for (int j = 0; j < 64; j++) {
            long long v = p64[j];
            if (v < 0 || v >= NN) { ok = 0; break; }
        }
        g_mode64 = ok;
    }
}

// ---------------- decode + degree count ----------------
__global__ void k_decode_count(const void* __restrict__ ei) {
    int e = blockIdx.x * blockDim.x + threadIdx.x;
    if (e >= ETOT) return;
    int s, d;
    if (e >= EE) { s = d = e - EE; }
    else if (g_mode64) {
        s = (int)((const long long*)ei)[e];
        d = (int)((const long long*)ei)[EE + e];
    } else {
        s = ((const int*)ei)[e];
        d = ((const int*)ei)[EE + e];
    }
    g_src[e] = s;
    g_dst[e] = d;
    atomicAdd(&g_deg[d], 1);
}

// ---------------- scan (re-zeroes g_deg for next replay) ----------------
#define SCAN_T 1024
#define SCAN_PER ((NN + SCAN_T - 1) / SCAN_T)
__global__ void k_scan() {
    __shared__ int s[SCAN_T];
    int t = threadIdx.x;
    int base = t * SCAN_PER;
    int deg[SCAN_PER];
    int sum = 0;
#pragma unroll
    for (int i = 0; i < SCAN_PER; i++) {
        int idx = base + i;
        deg[i] = (idx < NN) ? g_deg[idx] : 0;
        sum += deg[i];
        if (idx < NN) g_deg[idx] = 0;
    }
    s[t] = sum;
    __syncthreads();
    for (int o = 1; o < SCAN_T; o <<= 1) {
        int v = (t >= o) ? s[t - o] : 0;
        __syncthreads();
        s[t] += v;
        __syncthreads();
    }
    int run = s[t] - sum;
#pragma unroll
    for (int i = 0; i < SCAN_PER; i++) {
        int idx = base + i;
        if (idx < NN) {
            g_off[idx] = run;
            g_cur[idx] = run;
            run += deg[i];
        }
    }
    if (t == SCAN_T - 1) g_off[NN] = ETOT;
}

__global__ void k_fill() {
    int e = blockIdx.x * blockDim.x + threadIdx.x;
    if (e >= ETOT) return;
    int pos = atomicAdd(&g_cur[g_dst[e]], 1);
    g_csrc[pos] = g_src[e];
}

// ---------------- merged: transpose-pack W1,W2 (bf16 [n][k]) + convert x->bf16 ----------------
#define PACKB_W1 256
#define PACKB_W2 32
#define PACKB_X  2500
__global__ void k_pack_all(const float* __restrict__ W1l, const float* __restrict__ W1r,
                           const float* __restrict__ W2l, const float* __restrict__ W2r,
                           const float* __restrict__ x) {
    __shared__ float tile[32][33];
    int b = blockIdx.x;
    int tid = threadIdx.x;
    if (b < PACKB_W1) {
        int n0 = (b & 31) * 32, k0 = (b >> 5) * 32;
        int tx = tid & 31, ty = tid >> 5;
#pragma unroll
        for (int i = 0; i < 32; i += 8) {
            int k = k0 + ty + i, n = n0 + tx;
            float v = (n < F1) ? W1l[k * F1 + n] : W1r[k * F1 + (n - F1)];
            tile[ty + i][tx] = v;
        }
        __syncthreads();
#pragma unroll
        for (int i = 0; i < 32; i += 8) {
            int n = n0 + ty + i, k = k0 + tx;
            g_W1Tb[(size_t)n * DIN + k] = __float2bfloat16(tile[tx][ty + i]);
        }
    } else if (b < PACKB_W1 + PACKB_W2) {
        int r = b - PACKB_W1;
        int n0 = (r & 1) * 32, k0 = (r >> 1) * 32;
        int tx = tid & 31, ty = tid >> 5;
#pragma unroll
        for (int i = 0; i < 32; i += 8) {
            int k = k0 + ty + i, n = n0 + tx;
            float v = (n < DOUT) ? W2l[k * DOUT + n] : W2r[k * DOUT + (n - DOUT)];
            tile[ty + i][tx] = v;
        }
        __syncthreads();
#pragma unroll
        for (int i = 0; i < 32; i += 8) {
            int n = n0 + ty + i, k = k0 + tx;
            g_W2Tb[(size_t)n * F1 + k] = __float2bfloat16(tile[tx][ty + i]);
        }
    } else {
        int idx = (b - PACKB_W1 - PACKB_W2) * 1024 + tid * 4;
        float4 v = *(const float4*)(x + idx);
        __nv_bfloat162 p0 = __floats2bfloat162_rn(v.x, v.y);
        __nv_bfloat162 p1 = __floats2bfloat162_rn(v.z, v.w);
        uint2 pk;
        pk.x = *(unsigned*)&p0;
        pk.y = *(unsigned*)&p1;
        *(uint2*)(g_xb + idx) = pk;
    }
}

// ---------------- bf16 tensor-core GEMM (templated M/N tiles, cp.async 2-stage) ----------------
#define TBK 64
__device__ __forceinline__ void cp16(unsigned dst, const void* src, unsigned sz) {
    asm volatile("cp.async.cg.shared.global [%0], [%1], 16, %2;\n"
                 :: "r"(dst), "l"(src), "r"(sz));
}
__device__ __forceinline__ void ldsm_x4(unsigned& r0, unsigned& r1, unsigned& r2, unsigned& r3,
                                        const void* p) {
    unsigned addr = (unsigned)__cvta_generic_to_shared(p);
    asm volatile("ldmatrix.sync.aligned.m8n8.x4.shared.b16 {%0,%1,%2,%3}, [%4];"
                 : "=r"(r0), "=r"(r1), "=r"(r2), "=r"(r3) : "r"(addr));
}

template <int BN, int TM>
__global__ void __launch_bounds__((TM / 64) * (BN / 32) * 32) k_gemm_bf16(
    const __nv_bfloat16* __restrict__ A,
    const __nv_bfloat16* __restrict__ Bt, float* __restrict__ Cf,
    int M, int K, int ncols_bf, int cf_stride) {
    constexpr int MW = TM / 64;               // warp rows
    constexpr int NW = BN / 32;               // warp cols
    constexpr int T = MW * NW * 32;           // threads
    constexpr int A_BYTES = TM * 128;
    constexpr int STAGE = A_BYTES + BN * 128;
    extern __shared__ char smem[];

    int tid = threadIdx.x;
    int warp = tid >> 5, lane = tid & 31;
    int wm = (warp % MW) * 64;
    int wn = (warp / MW) * 32;
    int bm = blockIdx.y * TM, bn = blockIdx.x * BN;
    int tr = lane >> 2, tc = lane & 3;

    float acc[4][4][4];
#pragma unroll
    for (int mt = 0; mt < 4; mt++)
#pragma unroll
        for (int nt = 0; nt < 4; nt++)
#pragma unroll
            for (int r = 0; r < 4; r++) acc[mt][nt][r] = 0.f;

    auto fill = [&](int stage, int k0) {
        char* base = smem + stage * STAGE;
#pragma unroll
        for (int c = tid; c < TM * 8; c += T) {
            int row = c >> 3, ch = c & 7;
            unsigned valid = (bm + row < M) ? 16u : 0u;
            cp16((unsigned)__cvta_generic_to_shared(base + row * 128 + (((ch ^ (row & 7))) << 4)),
                 A + (size_t)(bm + row) * K + k0 + ch * 8, valid);
        }
#pragma unroll
        for (int c = tid; c < BN * 8; c += T) {
            int row = c >> 3, ch = c & 7;
            cp16((unsigned)__cvta_generic_to_shared(base + A_BYTES + row * 128 + (((ch ^ (row & 7))) << 4)),
                 Bt + (size_t)(bn + row) * K + k0 + ch * 8, 16u);
        }
        asm volatile("cp.async.commit_group;\n");
    };

    int KT = K / TBK;
    fill(0, 0);
    for (int kt = 0; kt < KT; kt++) {
        if (kt + 1 < KT) {
            fill((kt + 1) & 1, (kt + 1) * TBK);
            asm volatile("cp.async.wait_group 1;\n");
        } else {
            asm volatile("cp.async.wait_group 0;\n");
        }
        __syncthreads();

        char* Ab_s = smem + (kt & 1) * STAGE;
        char* Bb_s = Ab_s + A_BYTES;
#pragma unroll
        for (int ks = 0; ks < TBK / 16; ks++) {
            unsigned a[4][4];
#pragma unroll
            for (int mt = 0; mt < 4; mt++) {
                int row = wm + mt * 16 + (lane & 15);
                int chunk = ks * 2 + (lane >> 4);
                ldsm_x4(a[mt][0], a[mt][1], a[mt][2], a[mt][3],
                        Ab_s + row * 128 + ((chunk ^ (row & 7)) << 4));
            }
            unsigned b[4][2];
#pragma unroll
            for (int j = 0; j < 2; j++) {
                int row = wn + j * 16 + ((lane >> 4) << 3) + (lane & 7);
                int chunk = ks * 2 + ((lane >> 3) & 1);
                unsigned r0, r1, r2, r3;
                ldsm_x4(r0, r1, r2, r3,
                        Bb_s + row * 128 + ((chunk ^ (row & 7)) << 4));
                b[2 * j][0] = r0; b[2 * j][1] = r1;
                b[2 * j + 1][0] = r2; b[2 * j + 1][1] = r3;
            }
#pragma unroll
            for (int mt = 0; mt < 4; mt++)
#pragma unroll
                for (int nt = 0; nt < 4; nt++) {
                    asm volatile(
                        "mma.sync.aligned.m16n8k16.row.col.f32.bf16.bf16.f32 "
                        "{%0,%1,%2,%3}, {%4,%5,%6,%7}, {%8,%9}, {%0,%1,%2,%3};\n"
                        : "+f"(acc[mt][nt][0]), "+f"(acc[mt][nt][1]),
                          "+f"(acc[mt][nt][2]), "+f"(acc[mt][nt][3])
                        : "r"(a[mt][0]), "r"(a[mt][1]), "r"(a[mt][2]), "r"(a[mt][3]),
                          "r"(b[nt][0]), "r"(b[nt][1]));
                }
        }
        __syncthreads();
    }

    bool bf_side = (bn < ncols_bf);
#pragma unroll
    for (int mt = 0; mt < 4; mt++) {
        int row0 = bm + wm + mt * 16 + tr;
#pragma unroll
        for (int nt = 0; nt < 4; nt++) {
            int col0 = bn + wn + nt * 8 + 2 * tc;
            if (bf_side) {
                if (row0 < M)
                    g_xlb[(size_t)row0 * (F1 / 2) + (col0 >> 1)] =
                        __floats2bfloat162_rn(acc[mt][nt][0], acc[mt][nt][1]);
                if (row0 + 8 < M)
                    g_xlb[(size_t)(row0 + 8) * (F1 / 2) + (col0 >> 1)] =
                        __floats2bfloat162_rn(acc[mt][nt][2], acc[mt][nt][3]);
            } else {
                int c = col0 - ncols_bf;
                if (row0 < M)
                    *(float2*)(Cf + (size_t)row0 * cf_stride + c) =
                        make_float2(acc[mt][nt][0], acc[mt][nt][1]);
                if (row0 + 8 < M)
                    *(float2*)(Cf + (size_t)(row0 + 8) * cf_stride + c) =
                        make_float2(acc[mt][nt][2], acc[mt][nt][3]);
            }
        }
    }
}

// ---------------- fused layer-1 attention (bf16 gather, online softmax, 4x unroll) ----------------
__global__ void __launch_bounds__(128) k_l1_fused(const float* __restrict__ att1,
                                                  const float* __restrict__ b1) {
    int node = blockIdx.x;
    int c4 = threadIdx.x;                        // owns channels [4*c4, 4*c4+4)
    int beg = g_off[node], end = g_off[node + 1];

    float4 xr = *(const float4*)(g_xr + (size_t)node * F1 + c4 * 4);
    float4 aw = __ldg(&((const float4*)att1)[c4]);

    float m = -1e30f, den = 0.f;
    float4 acc = make_float4(0.f, 0.f, 0.f, 0.f);

    int p = beg;
    for (; p + 4 <= end; p += 4) {
        int s0 = g_csrc[p], s1 = g_csrc[p + 1], s2 = g_csrc[p + 2], s3 = g_csrc[p + 3];
        uint2 r0 = *(const uint2*)(g_xlb + (size_t)s0 * (F1 / 2) + c4 * 2);
        uint2 r1 = *(const uint2*)(g_xlb + (size_t)s1 * (F1 / 2) + c4 * 2);
        uint2 r2 = *(const uint2*)(g_xlb + (size_t)s2 * (F1 / 2) + c4 * 2);
        uint2 r3 = *(const uint2*)(g_xlb + (size_t)s3 * (F1 / 2) + c4 * 2);
        float2 a0 = __bfloat1622float2(*(const __nv_bfloat162*)&r0.x);
        float2 a1 = __bfloat1622float2(*(const __nv_bfloat162*)&r0.y);
        float2 b0 = __bfloat1622float2(*(const __nv_bfloat162*)&r1.x);
        float2 b1v = __bfloat1622float2(*(const __nv_bfloat162*)&r1.y);
        float2 c0 = __bfloat1622float2(*(const __nv_bfloat162*)&r2.x);
        float2 c1 = __bfloat1622float2(*(const __nv_bfloat162*)&r2.y);
        float2 d0 = __bfloat1622float2(*(const __nv_bfloat162*)&r3.x);
        float2 d1 = __bfloat1622float2(*(const __nv_bfloat162*)&r3.y);
        float p0 = lrelu(a0.x + xr.x) * aw.x + lrelu(a0.y + xr.y) * aw.y
                 + lrelu(a1.x + xr.z) * aw.z + lrelu(a1.y + xr.w) * aw.w;
        float p1 = lrelu(b0.x + xr.x) * aw.x + lrelu(b0.y + xr.y) * aw.y
                 + lrelu(b1v.x + xr.z) * aw.z + lrelu(b1v.y + xr.w) * aw.w;
        float p2 = lrelu(c0.x + xr.x) * aw.x + lrelu(c0.y + xr.y) * aw.y
                 + lrelu(c1.x + xr.z) * aw.z + lrelu(c1.y + xr.w) * aw.w;
        float p3 = lrelu(d0.x + xr.x) * aw.x + lrelu(d0.y + xr.y) * aw.y
                 + lrelu(d1.x + xr.z) * aw.z + lrelu(d1.y + xr.w) * aw.w;
#pragma unroll
        for (int o = 8; o; o >>= 1) {
            p0 += __shfl_xor_sync(0xffffffffu, p0, o);
            p1 += __shfl_xor_sync(0xffffffffu, p1, o);
            p2 += __shfl_xor_sync(0xffffffffu, p2, o);
            p3 += __shfl_xor_sync(0xffffffffu, p3, o);
        }
        float mx = fmaxf(fmaxf(p0, p1), fmaxf(p2, p3));
        if (mx > m) {
            float sc = __expf(m - mx);
            den *= sc;
            acc.x *= sc; acc.y *= sc; acc.z *= sc; acc.w *= sc;
            m = mx;
        }
        float w0 = __expf(p0 - m), w1 = __expf(p1 - m);
        float w2 = __expf(p2 - m), w3 = __expf(p3 - m);
        den += (w0 + w1) + (w2 + w3);
        acc.x += (w0 * a0.x + w1 * b0.x) + (w2 * c0.x + w3 * d0.x);
        acc.y += (w0 * a0.y + w1 * b0.y) + (w2 * c0.y + w3 * d0.y);
        acc.z += (w0 * a1.x + w1 * b1v.x) + (w2 * c1.x + w3 * d1.x);
        acc.w += (w0 * a1.y + w1 * b1v.y) + (w2 * c1.y + w3 * d1.y);
    }
    for (; p < end; p++) {
        int src = g_csrc[p];
        uint2 raw = *(const uint2*)(g_xlb + (size_t)src * (F1 / 2) + c4 * 2);
        float2 f0 = __bfloat1622float2(*(const __nv_bfloat162*)&raw.x);
        float2 f1 = __bfloat1622float2(*(const __nv_bfloat162*)&raw.y);
        float part = lrelu(f0.x + xr.x) * aw.x + lrelu(f0.y + xr.y) * aw.y
                   + lrelu(f1.x + xr.z) * aw.z + lrelu(f1.y + xr.w) * aw.w;
#pragma unroll
        for (int o = 8; o; o >>= 1)
            part += __shfl_xor_sync(0xffffffffu, part, o);
        if (part > m) {
            float sc = __expf(m - part);
            den *= sc;
            acc.x *= sc; acc.y *= sc; acc.z *= sc; acc.w *= sc;
            m = part;
        }
        float w = __expf(part - m);
        den += w;
        acc.x += w * f0.x; acc.y += w * f0.y; acc.z += w * f1.x; acc.w += w * f1.y;
    }
    float inv = 1.f / (den + 1e-16f);
    float4 bb = __ldg(&((const float4*)b1)[c4]);
    float r0 = acc.x * inv + bb.x;
    float r1 = acc.y * inv + bb.y;
    float r2 = acc.z * inv + bb.z;
    float r3 = acc.w * inv + bb.w;
    r0 = r0 > 0.f ? r0 : expm1f(r0);
    r1 = r1 > 0.f ? r1 : expm1f(r1);
    r2 = r2 > 0.f ? r2 : expm1f(r2);
    r3 = r3 > 0.f ? r3 : expm1f(r3);
    __nv_bfloat162 o0 = __floats2bfloat162_rn(r0, r1);
    __nv_bfloat162 o1 = __floats2bfloat162_rn(r2, r3);
    uint2 pk;
    pk.x = *(unsigned*)&o0;
    pk.y = *(unsigned*)&o1;
    *(uint2*)(g_h1b + (size_t)node * F1 + c4 * 4) = pk;
}

// ---------------- fused layer-2 attention + bias + log_softmax ----------------
__global__ void k_l2_fused(float* __restrict__ out, const float* __restrict__ att2,
                           const float* __restrict__ b2) {
    int node = (blockIdx.x * blockDim.x + threadIdx.x) >> 5;
    int lane = threadIdx.x & 31;
    if (node >= NN) return;
    int beg = g_off[node], end = g_off[node + 1];

    float xr = g_h2[(size_t)node * D2P + DOUT + lane];
    float aw = __ldg(att2 + lane);

    float m = -1e30f, den = 0.f, acc = 0.f;
    for (int p = beg; p < end; p++) {
        int src = g_csrc[p];
        float v = g_h2[(size_t)src * D2P + lane];
        float part = lrelu(v + xr) * aw;
#pragma unroll
        for (int o = 16; o; o >>= 1)
            part += __shfl_xor_sync(0xffffffffu, part, o);
        if (part > m) {
            float sc = __expf(m - part);
            den *= sc; acc *= sc; m = part;
        }
        float w = __expf(part - m);
        den += w;
        acc += w * v;
    }
    float v = acc / (den + 1e-16f) + __ldg(b2 + lane);
    float mx = v;
#pragma unroll
    for (int o = 16; o; o >>= 1) mx = fmaxf(mx, __shfl_xor_sync(0xffffffffu, mx, o));
    float s = __expf(v - mx);
#pragma unroll
    for (int o = 16; o; o >>= 1) s += __shfl_xor_sync(0xffffffffu, s, o);
    out[node * DOUT + lane] = v - mx - __logf(s);
}

// ---------------- launch ----------------
extern "C" void kernel_launch(void* const* d_in, const int* in_sizes, int n_in,
                              void* d_out, int out_size) {
    const float* x    = (const float*)d_in[0];
    const void*  ei   = d_in[1];
    const float* W1l  = (const float*)d_in[2];
    const float* W1r  = (const float*)d_in[3];
    const float* att1 = (const float*)d_in[4];
    const float* b1   = (const float*)d_in[5];
    const float* W2l  = (const float*)d_in[6];
    const float* W2r  = (const float*)d_in[7];
    const float* att2 = (const float*)d_in[8];
    const float* b2   = (const float*)d_in[9];
    float*       out  = (float*)d_out;

    const int TPB = 256;

    float *xr, *h2;
    __nv_bfloat16 *w1t, *w2t, *h1b, *xb;
    cudaGetSymbolAddress((void**)&xr,  g_xr);
    cudaGetSymbolAddress((void**)&h2,  g_h2);
    cudaGetSymbolAddress((void**)&w1t, g_W1Tb);
    cudaGetSymbolAddress((void**)&w2t, g_W2Tb);
    cudaGetSymbolAddress((void**)&h1b, g_h1b);
    cudaGetSymbolAddress((void**)&xb,  g_xb);

    const int SM1 = 2 * (128 * 128 + 128 * 128);   // 65536
    const int SM2 = 2 * (128 * 128 + 64 * 128);    // 49152
    cudaFuncSetAttribute(k_gemm_bf16<128, 128>, cudaFuncAttributeMaxDynamicSharedMemorySize, SM1);
    cudaFuncSetAttribute(k_gemm_bf16<64, 128>,  cudaFuncAttributeMaxDynamicSharedMemorySize, SM2);

    k_prep<<<1, 32>>>(ei);                                              // 1
    k_decode_count<<<(ETOT + TPB - 1) / TPB, TPB>>>(ei);                // 2
    k_pack_all<<<PACKB_W1 + PACKB_W2 + PACKB_X, TPB>>>(W1l, W1r, W2l, W2r, x); // 3
    {
        dim3 grid(F1P / 128, (NN + 127) / 128);
        k_gemm_bf16<128, 128><<<grid, 256, SM1>>>(xb, w1t, xr, NN, DIN, F1, F1); // 4
    }
    k_scan<<<1, SCAN_T>>>();                                            // 5
    k_fill<<<(ETOT + TPB - 1) / TPB, TPB>>>();                          // 6
    k_l1_fused<<<NN, 128>>>(att1, b1);                                  // 7
    {
        dim3 grid(1, (NN + 127) / 128);
        k_gemm_bf16<64, 128><<<grid, 128, SM2>>>(h1b, w2t, h2, NN, F1, 0, D2P); // 8
    }
    k_l2_fused<<<(NN * 32 + TPB - 1) / TPB, TPB>>>(out, att2, b2);      // 9
}